// round 8
// baseline (speedup 1.0000x reference)
#include <cuda_runtime.h>

#define TT   512
#define BB   2048
#define NTAG 16
#define LOG2E 1.4426950408889634f

// scratch: h sequence (T, B, 4) fp32 = 16.8 MB
__device__ float g_h[(size_t)TT * BB * 4];

__device__ __forceinline__ float rcp_ap(float x)  { float r; asm("rcp.approx.f32 %0, %1;"  : "=f"(r) : "f"(x)); return r; }
__device__ __forceinline__ float ex2_ap(float x)  { float r; asm("ex2.approx.f32 %0, %1;"  : "=f"(r) : "f"(x)); return r; }
__device__ __forceinline__ float lg2_ap(float x)  { float r; asm("lg2.approx.f32 %0, %1;"  : "=f"(r) : "f"(x)); return r; }
__device__ __forceinline__ float cos_ap(float x)  { float r; asm("cos.approx.f32 %0, %1;"  : "=f"(r) : "f"(x)); return r; }

// ---------------------------------------------------------------------------
// Kernel A: the LSTM recurrence. 4 lanes per batch chain (one per gate g).
// Identical numerics/structure to the best-known R4 kernel, except the
// 16-shfl gate exchange (128 issue-cyc on the SHFL pipe) is replaced with a
// double-buffered shared-memory exchange:
//   STS.128 (own v0..v3) + BAR.SYNC (1-warp block: ~3-7cyc, drains STS)
//   + 4x LDS.128 (all 4 gate rows of own quad)  ~= 25 issue-cyc.
// Quad stride = 20 floats (80B) so the 8 quads' row-s reads cover all 32
// banks exactly once -> conflict-free LDS.128.
// ---------------------------------------------------------------------------
__global__ void __launch_bounds__(32, 1)
recur_kernel(const float* __restrict__ x,
             const float* __restrict__ w_gates,
             const float* __restrict__ b_gates,
             const float* __restrict__ rx_theta)
{
    __shared__ __align__(16) float sx[2][160];       // 2 slots x 8 quads x 20 floats

    const int tid = blockIdx.x * 32 + threadIdx.x;   // 0..8191
    const int b   = tid >> 2;                        // batch chain 0..2047
    const int g   = tid & 3;                         // gate (f,i,g,o)
    const int q20 = ((threadIdx.x >> 2) & 7) * 20;   // quad base (floats)

    // per-lane weights: w_gates layout (4,4,12): [g*48 + k*12 + d]
    float wx[4][8], wh[4][4], th[4];
#pragma unroll
    for (int k = 0; k < 4; k++) {
#pragma unroll
        for (int d = 0; d < 8; d++) wx[k][d] = w_gates[g*48 + k*12 + d];
#pragma unroll
        for (int j = 0; j < 4; j++) wh[k][j] = w_gates[g*48 + k*12 + 8 + j];
        th[k] = b_gates[g*4 + k] + rx_theta[g*4 + k];
    }
    // lane 2 is the tanh gate; lanes 0,1,3 are sigmoid gates
    const float gm = (g == 2) ?  2.0f * LOG2E : -LOG2E;
    const float gA = (g == 2) ? -2.0f         :  1.0f;
    const float gB = (g == 2) ?  1.0f         :  0.0f;

    float h0 = 0.f, h1 = 0.f, h2 = 0.f, h3 = 0.f;
    float cx[4] = {0.f, 0.f, 0.f, 0.f};

    const float4* xp = (const float4*)x;             // (t*BB + b)*2 indexing
    float4 xa[4], xb[4];                             // 4-deep prefetch ring
#pragma unroll
    for (int p = 0; p < 4; p++) {
        size_t i = ((size_t)p * BB + b) * 2;
        xa[p] = xp[i]; xb[p] = xp[i + 1];
    }

    // x-part of pre for t=0 (one step ahead); consumes slot 0
    float xacc[4];
    {
        float xv[8] = {xa[0].x, xa[0].y, xa[0].z, xa[0].w,
                       xb[0].x, xb[0].y, xb[0].z, xb[0].w};
#pragma unroll
        for (int k = 0; k < 4; k++) {
            float qq = fmaf(xv[0], wx[k][0], th[k]);
            qq = fmaf(xv[1], wx[k][1], qq); qq = fmaf(xv[2], wx[k][2], qq);
            qq = fmaf(xv[3], wx[k][3], qq); qq = fmaf(xv[4], wx[k][4], qq);
            qq = fmaf(xv[5], wx[k][5], qq); qq = fmaf(xv[6], wx[k][6], qq);
            xacc[k] = fmaf(xv[7], wx[k][7], qq);
        }
    }
    // slot 0 is next used at t=3 to build xacc(t=4) -> must hold x[4]
    {
        size_t i4 = ((size_t)4 * BB + b) * 2;
        xa[0] = xp[i4]; xb[0] = xp[i4 + 1];
    }

    float4* hout = (float4*)g_h;

#pragma unroll 4
    for (int t = 0; t < TT; t++) {
        // ---- pre = xacc + Wh·h ; c = cos(pre) (h-critical path) ----
        float c0, c1, c2, c3;
        {
            float s0, s1;
            s0 = fmaf(h1, wh[0][1], fmaf(h0, wh[0][0], xacc[0]));
            s1 = fmaf(h3, wh[0][3], h2 * wh[0][2]);
            c0 = cos_ap(s0 + s1);
            s0 = fmaf(h1, wh[1][1], fmaf(h0, wh[1][0], xacc[1]));
            s1 = fmaf(h3, wh[1][3], h2 * wh[1][2]);
            c1 = cos_ap(s0 + s1);
            s0 = fmaf(h1, wh[2][1], fmaf(h0, wh[2][0], xacc[2]));
            s1 = fmaf(h3, wh[2][3], h2 * wh[2][2]);
            c2 = cos_ap(s0 + s1);
            s0 = fmaf(h1, wh[3][1], fmaf(h0, wh[3][0], xacc[3]));
            s1 = fmaf(h3, wh[3][3], h2 * wh[3][2]);
            c3 = cos_ap(s0 + s1);
        }

        // ---- off-path: compute next step's x-part, then refill the ring ----
        {
            int slot = (t + 1) & 3;
            float xv[8] = {xa[slot].x, xa[slot].y, xa[slot].z, xa[slot].w,
                           xb[slot].x, xb[slot].y, xb[slot].z, xb[slot].w};
#pragma unroll
            for (int k = 0; k < 4; k++) {
                float qq = fmaf(xv[0], wx[k][0], th[k]);
                qq = fmaf(xv[1], wx[k][1], qq); qq = fmaf(xv[2], wx[k][2], qq);
                qq = fmaf(xv[3], wx[k][3], qq); qq = fmaf(xv[4], wx[k][4], qq);
                qq = fmaf(xv[5], wx[k][5], qq); qq = fmaf(xv[6], wx[k][6], qq);
                xacc[k] = fmaf(xv[7], wx[k][7], qq);
            }
            int tp = t + 5; if (tp > TT - 1) tp = TT - 1;
            size_t i = ((size_t)tp * BB + b) * 2;
            xa[slot] = xp[i]; xb[slot] = xp[i + 1];
        }

        // ---- expvals: e0=c1c2c3, e1=c0c1, e2=e1c2, e3=e1t23 ----
        float t23 = c2 * c3;
        float e1  = c0 * c1;
        float e0  = c1 * t23;
        float e2  = e1 * c2;
        float e3  = e1 * t23;

        // ---- gate nonlinearity (exact): v = fma(A, rcp(ex2(m*e)+1), B) ----
        float v0 = fmaf(gA, rcp_ap(ex2_ap(gm * e0) + 1.0f), gB);
        float v1 = fmaf(gA, rcp_ap(ex2_ap(gm * e1) + 1.0f), gB);
        float v2 = fmaf(gA, rcp_ap(ex2_ap(gm * e2) + 1.0f), gB);
        float v3 = fmaf(gA, rcp_ap(ex2_ap(gm * e3) + 1.0f), gB);

        // ---- smem exchange (replaces 16 shfl) ----
        const int slot = t & 1;
        *(float4*)&sx[slot][q20 + g*4] = make_float4(v0, v1, v2, v3);
        __syncthreads();                              // 1-warp block: BAR floor, drains STS
        float4 row0 = *(const float4*)&sx[slot][q20 + 0];   // gate f: v of wires 0..3
        float4 row1 = *(const float4*)&sx[slot][q20 + 4];   // gate i
        float4 row2 = *(const float4*)&sx[slot][q20 + 8];   // gate g
        float4 row3 = *(const float4*)&sx[slot][q20 + 12];  // gate o

        // ---- combine (replicated in all lanes), identical math to R4 ----
        float hn[4];
        {
            float F, I, G, O, nc, E, r, tc;
            F=row0.x; I=row1.x; G=row2.x; O=row3.x;
            nc = fmaf(F, cx[0], I * G); cx[0] = nc;
            E = ex2_ap(nc * (2.0f * LOG2E)); r = rcp_ap(E + 1.0f);
            tc = fmaf(-2.0f, r, 1.0f); hn[0] = O * tc;
            F=row0.y; I=row1.y; G=row2.y; O=row3.y;
            nc = fmaf(F, cx[1], I * G); cx[1] = nc;
            E = ex2_ap(nc * (2.0f * LOG2E)); r = rcp_ap(E + 1.0f);
            tc = fmaf(-2.0f, r, 1.0f); hn[1] = O * tc;
            F=row0.z; I=row1.z; G=row2.z; O=row3.z;
            nc = fmaf(F, cx[2], I * G); cx[2] = nc;
            E = ex2_ap(nc * (2.0f * LOG2E)); r = rcp_ap(E + 1.0f);
            tc = fmaf(-2.0f, r, 1.0f); hn[2] = O * tc;
            F=row0.w; I=row1.w; G=row2.w; O=row3.w;
            nc = fmaf(F, cx[3], I * G); cx[3] = nc;
            E = ex2_ap(nc * (2.0f * LOG2E)); r = rcp_ap(E + 1.0f);
            tc = fmaf(-2.0f, r, 1.0f); hn[3] = O * tc;
        }
        h0 = hn[0]; h1 = hn[1]; h2 = hn[2]; h3 = hn[3];

        if (g == 0)
            hout[(size_t)t * BB + b] = make_float4(h0, h1, h2, h3);
    }
}

// ---------------------------------------------------------------------------
// Kernel B: logits + log_softmax. 2 threads per row-half (8 tags each),
// 4 rows per thread to amortize weight loads (L1 was the bottleneck);
// softmax max/sum joined via shfl_xor within the lane pair.
// ---------------------------------------------------------------------------
__global__ void __launch_bounds__(256)
out_kernel(const float* __restrict__ w_tag,
           const float* __restrict__ b_tag,
           float* __restrict__ out)
{
    const int NPAIR = TT * BB / 4;               // 262144 row-groups per iter
    int gt   = blockIdx.x * 256 + threadIdx.x;   // 0 .. 524287
    int p    = gt >> 1;                          // pair id = base row
    int half = gt & 1;

    const float4* wt = (const float4*)w_tag;     // 16 rows of float4
    float4 w[8];
#pragma unroll
    for (int j = 0; j < 8; j++) w[j] = wt[half*8 + j];
    float4 bta = ((const float4*)b_tag)[half*2];
    float4 btb = ((const float4*)b_tag)[half*2 + 1];
    float bt[8] = {bta.x, bta.y, bta.z, bta.w, btb.x, btb.y, btb.z, btb.w};

    const float4* hv4 = (const float4*)g_h;
    float4* o4 = (float4*)out;

#pragma unroll
    for (int it = 0; it < 4; it++) {
        int row = p + it * NPAIR;
        float4 hv = hv4[row];
        float lg[8];
#pragma unroll
        for (int j = 0; j < 8; j++)
            lg[j] = fmaf(w[j].w, hv.w, fmaf(w[j].z, hv.z, fmaf(w[j].y, hv.y, fmaf(w[j].x, hv.x, bt[j]))));

        float m = lg[0];
#pragma unroll
        for (int j = 1; j < 8; j++) m = fmaxf(m, lg[j]);
        m = fmaxf(m, __shfl_xor_sync(0xffffffffu, m, 1));

        float s = 0.f;
#pragma unroll
        for (int j = 0; j < 8; j++) s += ex2_ap((lg[j] - m) * LOG2E);
        s += __shfl_xor_sync(0xffffffffu, s, 1);

        float ls = fmaf(lg2_ap(s), 0.6931471805599453f, m);

        o4[(size_t)row*4 + half*2 + 0] = make_float4(lg[0]-ls, lg[1]-ls, lg[2]-ls, lg[3]-ls);
        o4[(size_t)row*4 + half*2 + 1] = make_float4(lg[4]-ls, lg[5]-ls, lg[6]-ls, lg[7]-ls);
    }
}

extern "C" void kernel_launch(void* const* d_in, const int* in_sizes, int n_in,
                              void* d_out, int out_size)
{
    const float* x        = (const float*)d_in[0];
    const float* w_gates  = (const float*)d_in[1];
    const float* b_gates  = (const float*)d_in[2];
    const float* rx_theta = (const float*)d_in[3];
    const float* w_tag    = (const float*)d_in[4];
    const float* b_tag    = (const float*)d_in[5];

    recur_kernel<<<256, 32>>>(x, w_gates, b_gates, rx_theta);   // 8192 threads (R4 layout)
    out_kernel<<<2048, 256>>>(w_tag, b_tag, (float*)d_out);     // 4 rows per thread-pair
}